// round 14
// baseline (speedup 1.0000x reference)
#include <cuda_runtime.h>
#include <cuda_fp16.h>
#include <stdint.h>

#define G       512
#define CDIM    512
#define TILE_M  64
#define THREADS 256

// ---- SMEM layout (per CTA; 2 CTAs/SM) ----
#define SM_A       0                        // 64 x 1024B, XOR-swizzled
#define SM_BBASE   65536                    // 6 slots x (16 x 512B) = 48KB
#define B_SLOT_SZ  8192
#define SM_QT      (SM_BBASE + 4 * B_SLOT_SZ)             // overlaid on slot 4 (8KB)
#define SM_CT      (SM_BBASE + 5 * B_SLOT_SZ)             // overlaid on slot 5 (2KB)
#define SM_PTS     (SM_BBASE + 6 * B_SLOT_SZ)             // 114688, 768B
#define SM_MBAR    (SM_PTS + 768)                         // 12 x 8B barriers
#define SM_TOTAL   (SM_MBAR + 128)                        // 115584 (x2 = 231168)

// fp16 image of latents: [b][k][c] row-major
__device__ __align__(16) unsigned char g_Bprep[4ull * G * CDIM * 2];

__device__ __forceinline__ uint32_t cvta_s(const void* p) {
    return (uint32_t)__cvta_generic_to_shared(const_cast<void*>(p));
}
__device__ __forceinline__ uint32_t pack_h2(float lo, float hi) {
    __half2 h = __floats2half2_rn(lo, hi);
    return *reinterpret_cast<uint32_t*>(&h);
}
__device__ __forceinline__ void ldsm_x4(uint32_t addr, uint32_t* r) {
    asm volatile("ldmatrix.sync.aligned.m8n8.x4.shared.b16 {%0,%1,%2,%3}, [%4];"
                 : "=r"(r[0]), "=r"(r[1]), "=r"(r[2]), "=r"(r[3]) : "r"(addr));
}
__device__ __forceinline__ void ldsm_x4_t(uint32_t addr, uint32_t* r) {
    asm volatile("ldmatrix.sync.aligned.m8n8.x4.trans.shared.b16 {%0,%1,%2,%3}, [%4];"
                 : "=r"(r[0]), "=r"(r[1]), "=r"(r[2]), "=r"(r[3]) : "r"(addr));
}
__device__ __forceinline__ void mma16816(float* d, const uint32_t* a, const uint32_t* b) {
    asm volatile(
        "mma.sync.aligned.m16n8k16.row.col.f32.f16.f16.f32 "
        "{%0,%1,%2,%3}, {%4,%5,%6,%7}, {%8,%9}, {%0,%1,%2,%3};"
        : "+f"(d[0]), "+f"(d[1]), "+f"(d[2]), "+f"(d[3])
        : "r"(a[0]), "r"(a[1]), "r"(a[2]), "r"(a[3]), "r"(b[0]), "r"(b[1]));
}
__device__ __forceinline__ void mbar_wait(uint32_t addr, uint32_t parity) {
    asm volatile(
        "{\n\t.reg .pred P;\n\t"
        "W_%=:\n\t"
        "mbarrier.try_wait.parity.acquire.cta.shared::cta.b64 P, [%0], %1, 0x989680;\n\t"
        "@!P bra W_%=;\n\t}"
        :: "r"(addr), "r"(parity) : "memory");
}
__device__ __forceinline__ void mbar_init(uint32_t addr, uint32_t cnt) {
    asm volatile("mbarrier.init.shared.b64 [%0], %1;" :: "r"(addr), "r"(cnt) : "memory");
}
__device__ __forceinline__ void mbar_arrive(uint32_t addr) {
    asm volatile("mbarrier.arrive.shared.b64 _, [%0];" :: "r"(addr) : "memory");
}
__device__ __forceinline__ void cpasync_arrive_noinc(uint32_t addr) {
    asm volatile("cp.async.mbarrier.arrive.noinc.shared::cta.b64 [%0];"
                 :: "r"(addr) : "memory");
}

// ---------- prep: elementwise fp32 -> fp16 convert of latents ----------
__global__ void rbf_prep(const float* __restrict__ lat) {
    int k = blockIdx.x, b = blockIdx.y;
    const float* src = lat + ((size_t)b * G + k) * CDIM;
    uint32_t* dst = (uint32_t*)(g_Bprep + ((size_t)b * G + k) * (CDIM * 2));
    int c2 = threadIdx.x;
    dst[c2] = pack_h2(src[2 * c2], src[2 * c2 + 1]);
}

// ---------- main kernel ----------
__global__ void __launch_bounds__(THREADS, 2)
rbf_main(const float* __restrict__ points, const float* __restrict__ eps,
         float* __restrict__ out, int Ntot)
{
    extern __shared__ __align__(1024) unsigned char smem[];
    const uint32_t sbase = cvta_s(smem);
    const int tid  = threadIdx.x;
    const int wid  = tid >> 5;
    const int lane = tid & 31;
    const int b    = blockIdx.y;
    const int n0   = blockIdx.x * TILE_M;
    const unsigned char* Bsrc = g_Bprep + (size_t)b * (G * CDIM * 2);

    const uint32_t mb_full  = sbase + SM_MBAR;        // 6 x 8B
    const uint32_t mb_empty = sbase + SM_MBAR + 48;   // 6 x 8B

    if (tid == 0) {
        #pragma unroll
        for (int s = 0; s < 6; ++s) {
            mbar_init(mb_full + s * 8, 32);            // one producer warp per slice
            mbar_init(mb_empty + s * 8, 8);            // one arrive per consumer warp
        }
    }
    __syncthreads();

    // slice s (0..63): cc = s>>5, k rows [16*(s&31), +16) -> slot s%6 (16 x 512B)
    // warp-wide issue: lane = 16B column chunk, j = row 0..15
    auto issue_slice_warp = [&](int s) {
        uint32_t dstbase = sbase + SM_BBASE + (uint32_t)(s % 6) * B_SLOT_SZ;
        int cc = s >> 5;
        const unsigned char* srow = Bsrc + ((size_t)((s & 31) * 16) * CDIM + cc * 256) * 2
                                    + (uint32_t)lane * 16;
        #pragma unroll
        for (int j = 0; j < 16; ++j) {
            const unsigned char* src = srow + (size_t)j * (CDIM * 2);
            uint32_t dst = dstbase + j * 512 + (uint32_t)((lane ^ (j & 7)) << 4);
            asm volatile("cp.async.cg.shared.global [%0], [%1], 16;" :: "r"(dst), "l"(src));
        }
    };

    // prefill slices 0..3 (slots 0..3; slots 4/5 hold tables until after A-gen)
    if (wid < 4) {
        issue_slice_warp(wid);
        cpasync_arrive_noinc(mb_full + wid * 8);
    }

    // stage points
    {
        const float* psrc = points + ((size_t)b * Ntot + n0) * 3;
        int nfl = min(TILE_M, Ntot - n0) * 3;
        float* stage = (float*)(smem + SM_PTS);
        for (int i = tid; i < TILE_M * 3; i += THREADS)
            stage[i] = (i < nfl) ? psrc[i] : 0.0f;
    }

    // per-k tables (overlaid on slots 4/5; dead before those slots are filled)
    {
        float4* qt = (float4*)(smem + SM_QT);
        float*  ct = (float*)(smem + SM_CT);
        const float LOG2E = 1.4426950408889634f;
        const float step  = 2.0f / 7.0f;
        for (int k = tid; k < G; k += THREADS) {
            float gx = -1.0f + step * (float)(k >> 6);
            float gy = -1.0f + step * (float)((k >> 3) & 7);
            float gz = -1.0f + step * (float)(k & 7);
            float e  = eps[k];
            float s  = -e * e * LOG2E;
            qt[k] = make_float4(-2.0f * s * gx, -2.0f * s * gy, -2.0f * s * gz, s);
            ct[k] = s * (gx * gx + gy * gy + gz * gz);
        }
    }
    __syncthreads();

    // A-gen: thread -> (row = tid&63, kq = tid>>6), 128 exps -> swizzled fp16 SMEM
    {
        const int row   = tid & 63;
        const int kbase = (tid >> 6) * 128;
        const float* stage = (const float*)(smem + SM_PTS);
        float px = stage[row * 3 + 0], py = stage[row * 3 + 1], pz = stage[row * 3 + 2];
        float p2 = px * px + py * py + pz * pz;
        const float4* qt = (const float4*)(smem + SM_QT);
        const float*  ct = (const float*)(smem + SM_CT);
        const uint32_t arow = sbase + SM_A + (uint32_t)row * 1024;
        const int swz = row & 7;
        #pragma unroll 4
        for (int j = 0; j < 16; ++j) {
            float ev[8];
            #pragma unroll
            for (int q = 0; q < 8; ++q) {
                int k = kbase + j * 8 + q;
                float4 qv = qt[k];
                float arg = fmaf(qv.x, px, fmaf(qv.y, py,
                            fmaf(qv.z, pz, fmaf(qv.w, p2, ct[k]))));
                asm("ex2.approx.f32 %0, %1;" : "=f"(ev[q]) : "f"(arg));
            }
            uint4 pk;
            pk.x = pack_h2(ev[0], ev[1]);
            pk.y = pack_h2(ev[2], ev[3]);
            pk.z = pack_h2(ev[4], ev[5]);
            pk.w = pack_h2(ev[6], ev[7]);
            int cj = (kbase >> 3) + j;
            asm volatile("st.shared.v4.b32 [%0], {%1,%2,%3,%4};"
                         :: "r"(arow + (uint32_t)((cj ^ swz) << 4)),
                            "r"(pk.x), "r"(pk.y), "r"(pk.z), "r"(pk.w));
        }
    }
    __syncthreads();                       // A visible; tables dead; slots 4/5 usable

    const int wm = (wid & 1) * 32;
    const int wn = (wid >> 1) * 64;
    const int hi = lane >> 4;

    // hoisted addressing
    uint32_t Abase[2], AswzX[2];
    #pragma unroll
    for (int tm = 0; tm < 2; ++tm) {
        int row = wm + tm * 16 + (lane & 15);
        Abase[tm] = sbase + SM_A + (uint32_t)row * 1024;
        AswzX[tm] = (uint32_t)(row & 7);
    }
    // B: 16-row slice; rr = lane&15
    uint32_t Boff[4];
    #pragma unroll
    for (int tn2 = 0; tn2 < 4; ++tn2) {
        int rr   = lane & 15;
        int colc = (wn + tn2 * 16 + hi * 8) >> 3;
        Boff[tn2] = (uint32_t)rr * 512 + (uint32_t)((colc ^ (rr & 7)) << 4);
    }

    float acc[2][8][4];
    #pragma unroll
    for (int tm = 0; tm < 2; ++tm)
        #pragma unroll
        for (int tn = 0; tn < 8; ++tn)
            #pragma unroll
            for (int q = 0; q < 4; ++q)
                acc[tm][tn][q] = 0.0f;

    for (int g = 0; g < 64; ++g) {
        const int slot = g % 6;
        mbar_wait(mb_full + slot * 8, (uint32_t)((g / 6) & 1));

        uint32_t Bb = sbase + SM_BBASE + (uint32_t)slot * B_SLOT_SZ;
        uint32_t c0 = (uint32_t)((g & 31) * 2 + hi);

        uint32_t af[2][4];
        #pragma unroll
        for (int tm = 0; tm < 2; ++tm)
            ldsm_x4(Abase[tm] + ((c0 ^ AswzX[tm]) << 4), af[tm]);
        uint32_t bf[4][4];
        #pragma unroll
        for (int t = 0; t < 4; ++t) {                  // rotated start per warp
            int tn2 = (t + wid) & 3;
            ldsm_x4_t(Bb + Boff[tn2], bf[tn2]);
        }
        #pragma unroll
        for (int tm = 0; tm < 2; ++tm)
            #pragma unroll
            for (int tn = 0; tn < 8; ++tn)
                mma16816(acc[tm][tn], af[tm], &bf[tn >> 1][(tn & 1) * 2]);

        if (lane == 0) mbar_arrive(mb_empty + slot * 8);

        // rotating producer: warp (g+4)&7 issues slice g+4 (slot last used by slice g-2)
        if (g + 4 < 64 && wid == ((g + 4) & 7)) {
            if (g >= 2)
                mbar_wait(mb_empty + ((g - 2) % 6) * 8, (uint32_t)(((g - 2) / 6) & 1));
            issue_slice_warp(g + 4);
            cpasync_arrive_noinc(mb_full + ((g + 4) % 6) * 8);
        }

        if (g == 31 || g == 63) {
            int cc = g >> 5;
            #pragma unroll
            for (int tm = 0; tm < 2; ++tm) {
                int rbase = n0 + wm + tm * 16 + (lane >> 2);
                #pragma unroll
                for (int half = 0; half < 2; ++half) {
                    int r = rbase + half * 8;
                    if (r < Ntot) {
                        float* op = out + ((size_t)b * Ntot + r) * CDIM
                                    + cc * 256 + wn + (lane & 3) * 2;
                        #pragma unroll
                        for (int tn = 0; tn < 8; ++tn) {
                            float2 v = make_float2(acc[tm][tn][half * 2],
                                                   acc[tm][tn][half * 2 + 1]);
                            *reinterpret_cast<float2*>(op + tn * 8) = v;
                        }
                    }
                }
            }
            if (g == 31) {
                #pragma unroll
                for (int tm = 0; tm < 2; ++tm)
                    #pragma unroll
                    for (int tn = 0; tn < 8; ++tn)
                        #pragma unroll
                        for (int q = 0; q < 4; ++q)
                            acc[tm][tn][q] = 0.0f;
            }
        }
    }
}

extern "C" void kernel_launch(void* const* d_in, const int* in_sizes, int n_in,
                              void* d_out, int out_size) {
    const float* points = (const float*)d_in[0];
    const float* lat    = (const float*)d_in[1];
    const float* eps    = (const float*)d_in[2];
    float* out = (float*)d_out;

    int B = in_sizes[1] / (G * CDIM);          // 4
    int N = in_sizes[0] / (3 * B);             // 50000

    cudaFuncSetAttribute(rbf_main, cudaFuncAttributeMaxDynamicSharedMemorySize, SM_TOTAL);

    rbf_prep<<<dim3(G, B), 256>>>(lat);
    rbf_main<<<dim3((N + TILE_M - 1) / TILE_M, B), THREADS, SM_TOTAL>>>(points, eps, out, N);
}

// round 15
// speedup vs baseline: 2.7825x; 2.7825x over previous
#include <cuda_runtime.h>
#include <cuda_fp16.h>
#include <stdint.h>

#define G       512
#define CDIM    512
#define TILE_M  128
#define THREADS 256

// ---- SMEM layout (1 CTA/SM) ----
#define SM_A       0                        // 128 x 1024B, XOR-swizzled = 131072
#define SM_BBASE   131072                   // 3 slots x (32 x 512B) = 49152
#define B_STAGE_SZ 16384
#define SM_QT      (SM_BBASE + 2 * B_STAGE_SZ)            // overlaid on slot 2 (8KB)
#define SM_CT      (SM_QT + 8192)                         // +2KB
#define SM_PTS     (SM_BBASE + 3 * B_STAGE_SZ)            // 180224, 1536B
#define SM_MBAR    (SM_PTS + 1536)                        // 6 x 8B barriers
#define SM_TOTAL   (SM_MBAR + 64)                         // 181824

// fp16 image of latents: [b][k][c] row-major
__device__ __align__(16) unsigned char g_Bprep[4ull * G * CDIM * 2];

__device__ __forceinline__ uint32_t cvta_s(const void* p) {
    return (uint32_t)__cvta_generic_to_shared(const_cast<void*>(p));
}
__device__ __forceinline__ uint32_t pack_h2(float lo, float hi) {
    __half2 h = __floats2half2_rn(lo, hi);
    return *reinterpret_cast<uint32_t*>(&h);
}
__device__ __forceinline__ void ldsm_x4(uint32_t addr, uint32_t* r) {
    asm volatile("ldmatrix.sync.aligned.m8n8.x4.shared.b16 {%0,%1,%2,%3}, [%4];"
                 : "=r"(r[0]), "=r"(r[1]), "=r"(r[2]), "=r"(r[3]) : "r"(addr));
}
__device__ __forceinline__ void ldsm_x4_t(uint32_t addr, uint32_t* r) {
    asm volatile("ldmatrix.sync.aligned.m8n8.x4.trans.shared.b16 {%0,%1,%2,%3}, [%4];"
                 : "=r"(r[0]), "=r"(r[1]), "=r"(r[2]), "=r"(r[3]) : "r"(addr));
}
__device__ __forceinline__ void mma16816(float* d, const uint32_t* a, const uint32_t* b) {
    asm volatile(
        "mma.sync.aligned.m16n8k16.row.col.f32.f16.f16.f32 "
        "{%0,%1,%2,%3}, {%4,%5,%6,%7}, {%8,%9}, {%0,%1,%2,%3};"
        : "+f"(d[0]), "+f"(d[1]), "+f"(d[2]), "+f"(d[3])
        : "r"(a[0]), "r"(a[1]), "r"(a[2]), "r"(a[3]), "r"(b[0]), "r"(b[1]));
}
__device__ __forceinline__ void mbar_wait(uint32_t addr, uint32_t parity) {
    asm volatile(
        "{\n\t.reg .pred P;\n\t"
        "W_%=:\n\t"
        "mbarrier.try_wait.parity.acquire.cta.shared::cta.b64 P, [%0], %1, 0x989680;\n\t"
        "@!P bra W_%=;\n\t}"
        :: "r"(addr), "r"(parity) : "memory");
}
__device__ __forceinline__ void mbar_init(uint32_t addr, uint32_t cnt) {
    asm volatile("mbarrier.init.shared.b64 [%0], %1;" :: "r"(addr), "r"(cnt) : "memory");
}
__device__ __forceinline__ void mbar_arrive(uint32_t addr) {
    asm volatile("mbarrier.arrive.shared.b64 _, [%0];" :: "r"(addr) : "memory");
}
__device__ __forceinline__ void cpasync_arrive_noinc(uint32_t addr) {
    asm volatile("cp.async.mbarrier.arrive.noinc.shared::cta.b64 [%0];"
                 :: "r"(addr) : "memory");
}

// ---------- prep: elementwise fp32 -> fp16 convert of latents ----------
__global__ void rbf_prep(const float* __restrict__ lat) {
    int k = blockIdx.x, b = blockIdx.y;
    const float* src = lat + ((size_t)b * G + k) * CDIM;
    uint32_t* dst = (uint32_t*)(g_Bprep + ((size_t)b * G + k) * (CDIM * 2));
    int c2 = threadIdx.x;
    dst[c2] = pack_h2(src[2 * c2], src[2 * c2 + 1]);
}

// ---------- main kernel ----------
__global__ void __launch_bounds__(THREADS, 1)
rbf_main(const float* __restrict__ points, const float* __restrict__ eps,
         float* __restrict__ out, int Ntot)
{
    extern __shared__ __align__(1024) unsigned char smem[];
    const uint32_t sbase = cvta_s(smem);
    const int tid  = threadIdx.x;
    const int wid  = tid >> 5;
    const int lane = tid & 31;
    const int b    = blockIdx.y;
    const int n0   = blockIdx.x * TILE_M;
    const unsigned char* Bsrc = g_Bprep + (size_t)b * (G * CDIM * 2);

    const uint32_t mb_full  = sbase + SM_MBAR;
    const uint32_t mb_empty = sbase + SM_MBAR + 24;

    if (tid == 0) {
        #pragma unroll
        for (int s = 0; s < 3; ++s) {
            mbar_init(mb_full + s * 8, THREADS);
            mbar_init(mb_empty + s * 8, 8);
        }
    }
    __syncthreads();

    // slice g (0..31): cc = g>>4, k rows [32*(g&15), +32), 256 cols -> slot g%3
    auto issue_slice = [&](int g) {
        uint32_t dstbase = sbase + SM_BBASE + (uint32_t)(g % 3) * B_STAGE_SZ;
        int cc = g >> 4;
        #pragma unroll
        for (int j = 0; j < 4; ++j) {
            int s  = tid + j * THREADS;
            int r  = s >> 5;
            int ch = s & 31;
            const unsigned char* src = Bsrc
                + ((size_t)(((g & 15) * 32) + r) * CDIM + cc * 256) * 2 + ch * 16;
            uint32_t dst = dstbase + r * 512 + (uint32_t)((ch ^ (r & 7)) << 4);
            asm volatile("cp.async.cg.shared.global [%0], [%1], 16;" :: "r"(dst), "l"(src));
        }
    };

    issue_slice(0); cpasync_arrive_noinc(mb_full + 0);
    issue_slice(1); cpasync_arrive_noinc(mb_full + 8);

    // stage points (128 rows)
    {
        const float* psrc = points + ((size_t)b * Ntot + n0) * 3;
        int nfl = min(TILE_M, Ntot - n0) * 3;
        float* stage = (float*)(smem + SM_PTS);
        for (int i = tid; i < TILE_M * 3; i += THREADS)
            stage[i] = (i < nfl) ? psrc[i] : 0.0f;
    }

    // per-k tables (overlaid on slot-2 buffer; dead before slice 2 is filled)
    {
        float4* qt = (float4*)(smem + SM_QT);
        float*  ct = (float*)(smem + SM_CT);
        const float LOG2E = 1.4426950408889634f;
        const float step  = 2.0f / 7.0f;
        for (int k = tid; k < G; k += THREADS) {
            float gx = -1.0f + step * (float)(k >> 6);
            float gy = -1.0f + step * (float)((k >> 3) & 7);
            float gz = -1.0f + step * (float)(k & 7);
            float e  = eps[k];
            float s  = -e * e * LOG2E;
            qt[k] = make_float4(-2.0f * s * gx, -2.0f * s * gy, -2.0f * s * gz, s);
            ct[k] = s * (gx * gx + gy * gy + gz * gz);
        }
    }
    __syncthreads();

    // A-gen: thread -> (row = tid&127, khalf = tid>>7), 256 exps -> swizzled fp16 SMEM
    {
        const int row   = tid & 127;
        const int kbase = (tid >> 7) * 256;
        const float* stage = (const float*)(smem + SM_PTS);
        float px = stage[row * 3 + 0], py = stage[row * 3 + 1], pz = stage[row * 3 + 2];
        float p2 = px * px + py * py + pz * pz;
        const float4* qt = (const float4*)(smem + SM_QT);
        const float*  ct = (const float*)(smem + SM_CT);
        const uint32_t arow = sbase + SM_A + (uint32_t)row * 1024;
        const int swz = row & 7;
        #pragma unroll 4
        for (int j = 0; j < 32; ++j) {
            float ev[8];
            #pragma unroll
            for (int q = 0; q < 8; ++q) {
                int k = kbase + j * 8 + q;
                float4 qv = qt[k];
                float arg = fmaf(qv.x, px, fmaf(qv.y, py,
                            fmaf(qv.z, pz, fmaf(qv.w, p2, ct[k]))));
                asm("ex2.approx.f32 %0, %1;" : "=f"(ev[q]) : "f"(arg));
            }
            uint4 pk;
            pk.x = pack_h2(ev[0], ev[1]);
            pk.y = pack_h2(ev[2], ev[3]);
            pk.z = pack_h2(ev[4], ev[5]);
            pk.w = pack_h2(ev[6], ev[7]);
            int cj = (kbase >> 3) + j;
            asm volatile("st.shared.v4.b32 [%0], {%1,%2,%3,%4};"
                         :: "r"(arow + (uint32_t)((cj ^ swz) << 4)),
                            "r"(pk.x), "r"(pk.y), "r"(pk.z), "r"(pk.w));
        }
    }
    __syncthreads();                       // A visible; tables dead; slice-2 fill may begin

    // warp grid: 2 M-warps x 4 N-warps; warp tile 64 x 64
    const int wm = (wid & 1) * 64;
    const int wn = (wid >> 1) * 64;
    const int hi = lane >> 4;

    // hoisted addressing
    uint32_t Abase[4], AswzX[4];
    #pragma unroll
    for (int tm = 0; tm < 4; ++tm) {
        int row = wm + tm * 16 + (lane & 15);
        Abase[tm] = sbase + SM_A + (uint32_t)row * 1024;
        AswzX[tm] = (uint32_t)(row & 7);
    }
    uint32_t Boff[2][4];
    #pragma unroll
    for (int kk = 0; kk < 2; ++kk)
        #pragma unroll
        for (int tn2 = 0; tn2 < 4; ++tn2) {
            int rr   = kk * 16 + (lane & 15);
            int colc = (wn + tn2 * 16 + hi * 8) >> 3;
            Boff[kk][tn2] = (uint32_t)rr * 512 + (uint32_t)((colc ^ (rr & 7)) << 4);
        }

    float acc[4][8][4];
    #pragma unroll
    for (int tm = 0; tm < 4; ++tm)
        #pragma unroll
        for (int tn = 0; tn < 8; ++tn)
            #pragma unroll
            for (int q = 0; q < 4; ++q)
                acc[tm][tn][q] = 0.0f;

    for (int g = 0; g < 32; ++g) {
        const int slot = g % 3;
        mbar_wait(mb_full + slot * 8, (uint32_t)((g / 3) & 1));

        uint32_t Bb = sbase + SM_BBASE + (uint32_t)slot * B_STAGE_SZ;
        uint32_t c0 = (uint32_t)((g & 15) * 4 + hi);
        #pragma unroll
        for (int kk = 0; kk < 2; ++kk) {
            uint32_t af[4][4];
            #pragma unroll
            for (int tm = 0; tm < 4; ++tm)
                ldsm_x4(Abase[tm] + (((c0 + kk * 2) ^ AswzX[tm]) << 4), af[tm]);
            uint32_t bf[4][4];
            #pragma unroll
            for (int tn2 = 0; tn2 < 4; ++tn2)
                ldsm_x4_t(Bb + Boff[kk][tn2], bf[tn2]);
            #pragma unroll
            for (int tm = 0; tm < 4; ++tm)
                #pragma unroll
                for (int tn = 0; tn < 8; ++tn)
                    mma16816(acc[tm][tn], af[tm], &bf[tn >> 1][(tn & 1) * 2]);
        }

        if (lane == 0) mbar_arrive(mb_empty + slot * 8);

        if (g + 2 < 32) {
            if (g >= 1)
                mbar_wait(mb_empty + ((g - 1) % 3) * 8, (uint32_t)(((g - 1) / 3) & 1));
            issue_slice(g + 2);
            cpasync_arrive_noinc(mb_full + ((g + 2) % 3) * 8);
        }

        if (g == 15 || g == 31) {
            int cc = g >> 4;
            #pragma unroll
            for (int tm = 0; tm < 4; ++tm) {
                int rbase = n0 + wm + tm * 16 + (lane >> 2);
                #pragma unroll
                for (int half = 0; half < 2; ++half) {
                    int r = rbase + half * 8;
                    if (r < Ntot) {
                        float* op = out + ((size_t)b * Ntot + r) * CDIM
                                    + cc * 256 + wn + (lane & 3) * 2;
                        #pragma unroll
                        for (int tn = 0; tn < 8; ++tn) {
                            float2 v = make_float2(acc[tm][tn][half * 2],
                                                   acc[tm][tn][half * 2 + 1]);
                            *reinterpret_cast<float2*>(op + tn * 8) = v;
                        }
                    }
                }
            }
            if (g == 15) {
                #pragma unroll
                for (int tm = 0; tm < 4; ++tm)
                    #pragma unroll
                    for (int tn = 0; tn < 8; ++tn)
                        #pragma unroll
                        for (int q = 0; q < 4; ++q)
                            acc[tm][tn][q] = 0.0f;
            }
        }
    }
}

extern "C" void kernel_launch(void* const* d_in, const int* in_sizes, int n_in,
                              void* d_out, int out_size) {
    const float* points = (const float*)d_in[0];
    const float* lat    = (const float*)d_in[1];
    const float* eps    = (const float*)d_in[2];
    float* out = (float*)d_out;

    int B = in_sizes[1] / (G * CDIM);          // 4
    int N = in_sizes[0] / (3 * B);             // 50000

    cudaFuncSetAttribute(rbf_main, cudaFuncAttributeMaxDynamicSharedMemorySize, SM_TOTAL);

    rbf_prep<<<dim3(G, B), 256>>>(lat);
    rbf_main<<<dim3((N + TILE_M - 1) / TILE_M, B), THREADS, SM_TOTAL>>>(points, eps, out, N);
}